// round 6
// baseline (speedup 1.0000x reference)
#include <cuda_runtime.h>
#include <cuda_bf16.h>
#include <stdint.h>
#include <math.h>

#define N_TOK 8192
#define C_DIM 1024
#define H_DIM 4096
#define E_NUM 5
#define PADDED_CAP (N_TOK + E_NUM * 128)   // 8832

// ---------------------------------------------------------------------------
// Device scratch (allocation-free per harness rules)
// ---------------------------------------------------------------------------
__device__ float g_h[(size_t)N_TOK * C_DIM];                       // layernormed tokens (fp32)
__device__ float g_act[(size_t)PADDED_CAP * H_DIM];                // relu^2 activations (fp32)
__device__ float g_scale[N_TOK];
__device__ int   g_sorted[N_TOK];
__device__ int   g_count[E_NUM];
__device__ int   g_offset[E_NUM + 1];
__device__ int   g_poff[E_NUM + 1];
__device__ int   g_cursor[E_NUM];

// pre-converted transposed weights: [E][n][k] bf16 (hi and lo planes)
__device__ __align__(16) __nv_bfloat16 g_w1t_hi[(size_t)E_NUM * H_DIM * C_DIM];
__device__ __align__(16) __nv_bfloat16 g_w1t_lo[(size_t)E_NUM * H_DIM * C_DIM];
__device__ __align__(16) __nv_bfloat16 g_w2t_hi[(size_t)E_NUM * C_DIM * H_DIM];
__device__ __align__(16) __nv_bfloat16 g_w2t_lo[(size_t)E_NUM * C_DIM * H_DIM];

// ---------------------------------------------------------------------------
// PTX helpers
// ---------------------------------------------------------------------------
__device__ __forceinline__ uint32_t smem_u32(const void* p) {
    uint32_t a;
    asm("{ .reg .u64 t; cvta.to.shared.u64 t, %1; cvt.u32.u64 %0, t; }" : "=r"(a) : "l"(p));
    return a;
}
__device__ __forceinline__ uint32_t lds32(uint32_t a) {
    uint32_t v;
    asm volatile("ld.shared.b32 %0, [%1];" : "=r"(v) : "r"(a));
    return v;
}
__device__ __forceinline__ void mma16816(float* c, const uint32_t* a, uint32_t b0, uint32_t b1) {
    asm volatile("mma.sync.aligned.m16n8k16.row.col.f32.bf16.bf16.f32 "
                 "{%0,%1,%2,%3}, {%4,%5,%6,%7}, {%8,%9}, {%0,%1,%2,%3};"
                 : "+f"(c[0]), "+f"(c[1]), "+f"(c[2]), "+f"(c[3])
                 : "r"(a[0]), "r"(a[1]), "r"(a[2]), "r"(a[3]), "r"(b0), "r"(b1));
}
__device__ __forceinline__ uint32_t pack_hi(float x, float y) {
    __nv_bfloat162 p; p.x = __float2bfloat16(x); p.y = __float2bfloat16(y);
    return *reinterpret_cast<uint32_t*>(&p);
}
__device__ __forceinline__ uint32_t pack_lo(float x, float y) {
    __nv_bfloat16 hx = __float2bfloat16(x), hy = __float2bfloat16(y);
    __nv_bfloat162 p;
    p.x = __float2bfloat16(x - __bfloat162float(hx));
    p.y = __float2bfloat16(y - __bfloat162float(hy));
    return *reinterpret_cast<uint32_t*>(&p);
}

// ---------------------------------------------------------------------------
// Small pipeline kernels (R5-validated patterns)
// ---------------------------------------------------------------------------
__global__ void init_kernel() {
    if (threadIdx.x < E_NUM) { g_count[threadIdx.x] = 0; g_cursor[threadIdx.x] = 0; }
}

__global__ void __launch_bounds__(256) ln_conf_kernel(
    const float* __restrict__ x, const int* __restrict__ winners,
    const float* __restrict__ gamma, const float* __restrict__ beta,
    const float* __restrict__ wc, const float* __restrict__ bc)
{
    int n = blockIdx.x, tid = threadIdx.x;
    const float* xr = x + (size_t)n * C_DIM;
    float xv[4], s = 0.f, s2 = 0.f;
#pragma unroll
    for (int i = 0; i < 4; i++) { float v = xr[tid + 256 * i]; xv[i] = v; s += v; s2 += v * v; }
#pragma unroll
    for (int off = 16; off > 0; off >>= 1) {
        s  += __shfl_down_sync(0xffffffffu, s,  off);
        s2 += __shfl_down_sync(0xffffffffu, s2, off);
    }
    __shared__ float sh1[8], sh2[8];
    __shared__ float s_mean, s_rstd;
    int warp = tid >> 5, lane = tid & 31;
    if (lane == 0) { sh1[warp] = s; sh2[warp] = s2; }
    __syncthreads();
    if (tid == 0) {
        float ts = 0.f, ts2 = 0.f;
#pragma unroll
        for (int w = 0; w < 8; w++) { ts += sh1[w]; ts2 += sh2[w]; }
        float mean = ts * (1.f / C_DIM);
        float var = ts2 * (1.f / C_DIM) - mean * mean;
        s_mean = mean; s_rstd = rsqrtf(var + 1e-5f);
    }
    __syncthreads();
    float mean = s_mean, rstd = s_rstd;
    int win = winners[n];
    const float* wcr = wc + (size_t)win * C_DIM;
    float dot = 0.f;
#pragma unroll
    for (int i = 0; i < 4; i++) {
        int c = tid + 256 * i;
        float hv = (xv[i] - mean) * rstd * gamma[c] + beta[c];
        g_h[(size_t)n * C_DIM + c] = hv;
        dot += hv * wcr[c];
    }
#pragma unroll
    for (int off = 16; off > 0; off >>= 1) dot += __shfl_down_sync(0xffffffffu, dot, off);
    if (lane == 0) sh1[warp] = dot;
    __syncthreads();
    if (tid == 0) {
        float t = 0.f;
#pragma unroll
        for (int w = 0; w < 8; w++) t += sh1[w];
        t += bc[win];
        float conf = 1.f / (1.f + expf(-t));
        g_scale[n] = conf / (conf + 1e-6f);
        atomicAdd(&g_count[win], 1);
    }
}

__global__ void scan_kernel() {
    if (threadIdx.x == 0) {
        int acc = 0, pacc = 0;
        g_offset[0] = 0; g_poff[0] = 0;
        for (int e = 0; e < E_NUM; e++) {
            int c = g_count[e];
            acc += c;
            g_offset[e + 1] = acc;
            g_cursor[e] = g_offset[e];
            pacc += ((c + 127) / 128) * 128;
            g_poff[e + 1] = pacc;
        }
    }
}

__global__ void scatter_kernel(const int* __restrict__ winners) {
    int n = blockIdx.x * blockDim.x + threadIdx.x;
    if (n < N_TOK) {
        int e = winners[n];
        int pos = atomicAdd(&g_cursor[e], 1);
        g_sorted[pos] = n;
    }
}

// ---------------------------------------------------------------------------
// transpose + bf16 hi/lo convert: src [E][R][Cc] fp32 -> dst [E][Cc][R] bf16
// ---------------------------------------------------------------------------
__global__ void __launch_bounds__(256) tr_w(
    const float* __restrict__ src, __nv_bfloat16* __restrict__ dhi,
    __nv_bfloat16* __restrict__ dlo, int R, int Cc)
{
    __shared__ float t[32][33];
    size_t eoff = (size_t)blockIdx.z * R * Cc;
    const float* S = src + eoff;
    __nv_bfloat16* Dh = dhi + eoff;
    __nv_bfloat16* Dl = dlo + eoff;
    int bx = blockIdx.x * 32;   // Cc (output-feature) dim
    int by = blockIdx.y * 32;   // R  (k) dim
    int tx = threadIdx.x & 31, ty = threadIdx.x >> 5;
#pragma unroll
    for (int q = 0; q < 4; q++)
        t[ty + q * 8][tx] = S[(size_t)(by + ty + q * 8) * Cc + bx + tx];
    __syncthreads();
#pragma unroll
    for (int q = 0; q < 4; q++) {
        float v = t[tx][ty + q * 8];
        size_t o = (size_t)(bx + ty + q * 8) * R + by + tx;
        __nv_bfloat16 h = __float2bfloat16(v);
        Dh[o] = h;
        Dl[o] = __float2bfloat16(v - __bfloat162float(h));
    }
}

// ---------------------------------------------------------------------------
// HMMA GEMM. CTA 128x128, BK=32, 8 warps (2M x 4N), warp tile 64x32.
// A: fp32 LDG + in-kernel hi/lo split (R5-validated path).
// B: pre-converted transposed bf16 hi/lo, LDG.128 register prefetch + STS.128.
// Smem planes (80B row stride): Ahi | Alo | Bhi | Blo. A: [m][k], B: [n][k].
// ---------------------------------------------------------------------------
#define BK 32
#define ROW_STRIDE 80
#define PLANE_B (128 * ROW_STRIDE)   // 10240
#define STAGE_B (4 * PLANE_B)        // 40960

template<bool G1>
__global__ void __launch_bounds__(256, 1) gemm_mma(
    const __nv_bfloat16* __restrict__ bt_hi,
    const __nv_bfloat16* __restrict__ bt_lo,
    const float* __restrict__ x,
    float* __restrict__ out)
{
    constexpr int K  = G1 ? C_DIM : H_DIM;   // reduction dim
    constexpr int NC = K / BK;

    int e     = blockIdx.z;
    int pbase = g_poff[e];
    int pcnt  = g_poff[e + 1] - pbase;
    int row0  = blockIdx.y * 128;
    if (row0 >= pcnt) return;
    int coln0 = blockIdx.x * 128;
    int prow0 = pbase + row0;

    __shared__ __align__(16) char sm[STAGE_B];
    uint32_t sb = smem_u32(sm);

    int tid = threadIdx.x, lane = tid & 31, wid = tid >> 5;
    int wm = wid & 1, wn = wid >> 1;
    int g4 = lane >> 2, t4 = lane & 3;

    int obase = g_offset[e];
    int cnt   = g_offset[e + 1] - obase;

    // ---- A source rows: 4 rows per thread, k-quarter kq (R5 pattern) ----
    int kq = tid & 7;
    const float* asrc[4];
#pragma unroll
    for (int p = 0; p < 4; p++) {
        int m = p * 32 + (tid >> 3);
        if (G1) {
            int gr = row0 + m;
            asrc[p] = (gr < cnt) ? (g_h + (size_t)g_sorted[obase + gr] * C_DIM) : 0;
        } else {
            asrc[p] = g_act + (size_t)(prow0 + m) * H_DIM;
        }
    }
    // ---- B source: transposed bf16 [n][k]; thread covers row tid>>1, 2 chunks ----
    int brow = tid >> 1;                  // 0..127
    int bq2  = (tid & 1) * 2;             // 16B-chunk pair start (q = bq2, bq2+1)
    const __nv_bfloat16* bsrc_hi = bt_hi + (size_t)e * C_DIM * H_DIM
                                 + (size_t)(coln0 + brow) * K + bq2 * 8;
    const __nv_bfloat16* bsrc_lo = bt_lo + (size_t)e * C_DIM * H_DIM
                                 + (size_t)(coln0 + brow) * K + bq2 * 8;
    uint32_t bsts = (uint32_t)(brow * ROW_STRIDE + bq2 * 16);

    float acc[4][4][4];
#pragma unroll
    for (int i = 0; i < 4; i++)
#pragma unroll
        for (int j = 0; j < 4; j++)
#pragma unroll
            for (int q = 0; q < 4; q++) acc[i][j][q] = 0.f;

    // register prefetch buffers
    float4 ra[4];
    uint4  rbh[2], rbl[2];

    // preload chunk 0
#pragma unroll
    for (int p = 0; p < 4; p++)
        ra[p] = asrc[p] ? *reinterpret_cast<const float4*>(asrc[p] + 4 * kq)
                        : make_float4(0.f, 0.f, 0.f, 0.f);
    rbh[0] = *reinterpret_cast<const uint4*>(bsrc_hi);
    rbh[1] = *reinterpret_cast<const uint4*>(bsrc_hi + 8);
    rbl[0] = *reinterpret_cast<const uint4*>(bsrc_lo);
    rbl[1] = *reinterpret_cast<const uint4*>(bsrc_lo + 8);

#pragma unroll 1
    for (int c = 0; c < NC; c++) {
        __syncthreads();   // previous chunk's readers done

        // STS current registers (A: convert fp32 -> hi/lo; B: raw copy)
#pragma unroll
        for (int p = 0; p < 4; p++) {
            int m = p * 32 + (tid >> 3);
            uint32_t off = (uint32_t)(m * ROW_STRIDE + 8 * kq);
            uint2 hv, lv;
            hv.x = pack_hi(ra[p].x, ra[p].y); hv.y = pack_hi(ra[p].z, ra[p].w);
            lv.x = pack_lo(ra[p].x, ra[p].y); lv.y = pack_lo(ra[p].z, ra[p].w);
            *reinterpret_cast<uint2*>(sm + off)           = hv;
            *reinterpret_cast<uint2*>(sm + PLANE_B + off) = lv;
        }
        *reinterpret_cast<uint4*>(sm + 2 * PLANE_B + bsts)      = rbh[0];
        *reinterpret_cast<uint4*>(sm + 2 * PLANE_B + bsts + 16) = rbh[1];
        *reinterpret_cast<uint4*>(sm + 3 * PLANE_B + bsts)      = rbl[0];
        *reinterpret_cast<uint4*>(sm + 3 * PLANE_B + bsts + 16) = rbl[1];

        // issue LDGs for next chunk
        if (c + 1 < NC) {
            int k0 = (c + 1) * BK;
#pragma unroll
            for (int p = 0; p < 4; p++)
                ra[p] = asrc[p] ? *reinterpret_cast<const float4*>(asrc[p] + k0 + 4 * kq)
                                : make_float4(0.f, 0.f, 0.f, 0.f);
            rbh[0] = *reinterpret_cast<const uint4*>(bsrc_hi + k0);
            rbh[1] = *reinterpret_cast<const uint4*>(bsrc_hi + k0 + 8);
            rbl[0] = *reinterpret_cast<const uint4*>(bsrc_lo + k0);
            rbl[1] = *reinterpret_cast<const uint4*>(bsrc_lo + k0 + 8);
        }

        __syncthreads();   // smem tile complete

        // ---- compute (R4/R5-validated m16n8k16 fragment layout) ----
#pragma unroll
        for (int ks = 0; ks < 2; ks++) {
            uint32_t ahi[4][4], alo[4][4];
#pragma unroll
            for (int mi = 0; mi < 4; mi++) {
                uint32_t base = sb + (uint32_t)((wm * 64 + mi * 16 + g4) * ROW_STRIDE + ks * 32 + t4 * 4);
                ahi[mi][0] = lds32(base);
                ahi[mi][1] = lds32(base + 8 * ROW_STRIDE);
                ahi[mi][2] = lds32(base + 16);
                ahi[mi][3] = lds32(base + 8 * ROW_STRIDE + 16);
                uint32_t basel = base + PLANE_B;
                alo[mi][0] = lds32(basel);
                alo[mi][1] = lds32(basel + 8 * ROW_STRIDE);
                alo[mi][2] = lds32(basel + 16);
                alo[mi][3] = lds32(basel + 8 * ROW_STRIDE + 16);
            }
            uint32_t bhi[4][2], blo[4][2];
#pragma unroll
            for (int nt = 0; nt < 4; nt++) {
                uint32_t bb = sb + (uint32_t)(2 * PLANE_B + (wn * 32 + nt * 8 + g4) * ROW_STRIDE + ks * 32 + t4 * 4);
                bhi[nt][0] = lds32(bb);
                bhi[nt][1] = lds32(bb + 16);
                blo[nt][0] = lds32(bb + PLANE_B);
                blo[nt][1] = lds32(bb + PLANE_B + 16);
            }
#pragma unroll
            for (int mi = 0; mi < 4; mi++)
#pragma unroll
                for (int nt = 0; nt < 4; nt++) {
                    float* cc = acc[mi][nt];
                    mma16816(cc, ahi[mi], bhi[nt][0], bhi[nt][1]);
                    mma16816(cc, alo[mi], bhi[nt][0], bhi[nt][1]);
                    mma16816(cc, ahi[mi], blo[nt][0], blo[nt][1]);
                }
        }
    }

    // ---- epilogue (unchanged from R5) ----
    if (G1) {
#pragma unroll
        for (int mi = 0; mi < 4; mi++) {
            int gr = wm * 64 + mi * 16 + g4;
            size_t r0g = (size_t)(prow0 + gr)     * H_DIM;
            size_t r1g = (size_t)(prow0 + gr + 8) * H_DIM;
#pragma unroll
            for (int nt = 0; nt < 4; nt++) {
                int gc = coln0 + wn * 32 + nt * 8 + t4 * 2;
                float* cc = acc[mi][nt];
                float2 v0, v1;
                v0.x = fmaxf(cc[0], 0.f); v0.x *= v0.x;
                v0.y = fmaxf(cc[1], 0.f); v0.y *= v0.y;
                v1.x = fmaxf(cc[2], 0.f); v1.x *= v1.x;
                v1.y = fmaxf(cc[3], 0.f); v1.y *= v1.y;
                *reinterpret_cast<float2*>(g_act + r0g + gc) = v0;
                *reinterpret_cast<float2*>(g_act + r1g + gc) = v1;
            }
        }
    } else {
#pragma unroll
        for (int mi = 0; mi < 4; mi++) {
            int rl0 = row0 + wm * 64 + mi * 16 + g4;
            int tok0 = -1, tok1 = -1;
            float sc0 = 0.f, sc1 = 0.f;
            if (rl0 < cnt)     { tok0 = g_sorted[obase + rl0];     sc0 = g_scale[tok0]; }
            if (rl0 + 8 < cnt) { tok1 = g_sorted[obase + rl0 + 8]; sc1 = g_scale[tok1]; }
#pragma unroll
            for (int nt = 0; nt < 4; nt++) {
                int gc = coln0 + wn * 32 + nt * 8 + t4 * 2;
                float* cc = acc[mi][nt];
                if (tok0 >= 0) {
                    size_t o = (size_t)tok0 * C_DIM + gc;
                    float2 xv = *reinterpret_cast<const float2*>(x + o);
                    float2 ov; ov.x = xv.x + cc[0] * sc0; ov.y = xv.y + cc[1] * sc0;
                    *reinterpret_cast<float2*>(out + o) = ov;
                }
                if (tok1 >= 0) {
                    size_t o = (size_t)tok1 * C_DIM + gc;
                    float2 xv = *reinterpret_cast<const float2*>(x + o);
                    float2 ov; ov.x = xv.x + cc[2] * sc1; ov.y = xv.y + cc[3] * sc1;
                    *reinterpret_cast<float2*>(out + o) = ov;
                }
            }
        }
    }
}

// ---------------------------------------------------------------------------
extern "C" void kernel_launch(void* const* d_in, const int* in_sizes, int n_in,
                              void* d_out, int out_size)
{
    const float* x       = (const float*)d_in[0];
    const int*   winners = (const int*)  d_in[1];
    const float* gamma   = (const float*)d_in[2];
    const float* beta    = (const float*)d_in[3];
    const float* w1      = (const float*)d_in[4];
    const float* w2      = (const float*)d_in[5];
    const float* wc      = (const float*)d_in[6];
    const float* bc      = (const float*)d_in[7];
    float* out = (float*)d_out;

    init_kernel<<<1, 32>>>();
    ln_conf_kernel<<<N_TOK, 256>>>(x, winners, gamma, beta, wc, bc);
    scan_kernel<<<1, 32>>>();
    scatter_kernel<<<N_TOK / 256, 256>>>(winners);

    // w1 [E][C][H] -> [E][H][C] (R=C rows, Cc=H)
    tr_w<<<dim3(H_DIM / 32, C_DIM / 32, E_NUM), 256>>>(w1, g_w1t_hi, g_w1t_lo, C_DIM, H_DIM);
    // w2 [E][H][C] -> [E][C][H] (R=H rows, Cc=C)
    tr_w<<<dim3(C_DIM / 32, H_DIM / 32, E_NUM), 256>>>(w2, g_w2t_hi, g_w2t_lo, H_DIM, C_DIM);

    gemm_mma<true><<<dim3(H_DIM / 128, PADDED_CAP / 128, E_NUM), 256>>>(g_w1t_hi, g_w1t_lo, x, out);
    gemm_mma<false><<<dim3(C_DIM / 128, PADDED_CAP / 128, E_NUM), 256>>>(g_w2t_hi, g_w2t_lo, x, out);
}

// round 7
// speedup vs baseline: 11.2389x; 11.2389x over previous
#include <cuda_runtime.h>
#include <cuda_bf16.h>
#include <stdint.h>
#include <math.h>

#define N_TOK 8192
#define C_DIM 1024
#define H_DIM 4096
#define E_NUM 5
#define PADDED_CAP (N_TOK + E_NUM * 128)   // 8832

// ---------------------------------------------------------------------------
// Device scratch (allocation-free per harness rules)
// ---------------------------------------------------------------------------
__device__ float g_h[(size_t)N_TOK * C_DIM];                       // layernormed tokens (fp32)
__device__ float g_act[(size_t)PADDED_CAP * H_DIM];                // relu^2 activations (fp32)
__device__ float g_scale[N_TOK];
__device__ int   g_sorted[N_TOK];
__device__ int   g_count[E_NUM];
__device__ int   g_offset[E_NUM + 1];
__device__ int   g_poff[E_NUM + 1];
__device__ int   g_cursor[E_NUM];

// ---------------------------------------------------------------------------
// PTX helpers
// ---------------------------------------------------------------------------
__device__ __forceinline__ uint32_t smem_u32(const void* p) {
    uint32_t a;
    asm("{ .reg .u64 t; cvta.to.shared.u64 t, %1; cvt.u32.u64 %0, t; }" : "=r"(a) : "l"(p));
    return a;
}
__device__ __forceinline__ uint32_t lds32(uint32_t a) {
    uint32_t v;
    asm volatile("ld.shared.b32 %0, [%1];" : "=r"(v) : "r"(a));
    return v;
}
__device__ __forceinline__ void mma16816(float* c, const uint32_t* a, uint32_t b0, uint32_t b1) {
    asm volatile("mma.sync.aligned.m16n8k16.row.col.f32.bf16.bf16.f32 "
                 "{%0,%1,%2,%3}, {%4,%5,%6,%7}, {%8,%9}, {%0,%1,%2,%3};"
                 : "+f"(c[0]), "+f"(c[1]), "+f"(c[2]), "+f"(c[3])
                 : "r"(a[0]), "r"(a[1]), "r"(a[2]), "r"(a[3]), "r"(b0), "r"(b1));
}
__device__ __forceinline__ uint32_t pack_hi(float x, float y) {
    __nv_bfloat162 p; p.x = __float2bfloat16(x); p.y = __float2bfloat16(y);
    return *reinterpret_cast<uint32_t*>(&p);
}
__device__ __forceinline__ uint32_t pack_lo(float x, float y) {
    __nv_bfloat16 hx = __float2bfloat16(x), hy = __float2bfloat16(y);
    __nv_bfloat162 p;
    p.x = __float2bfloat16(x - __bfloat162float(hx));
    p.y = __float2bfloat16(y - __bfloat162float(hy));
    return *reinterpret_cast<uint32_t*>(&p);
}

// ---------------------------------------------------------------------------
// Small pipeline kernels (validated)
// ---------------------------------------------------------------------------
__global__ void init_kernel() {
    if (threadIdx.x < E_NUM) { g_count[threadIdx.x] = 0; g_cursor[threadIdx.x] = 0; }
}

__global__ void __launch_bounds__(256) ln_conf_kernel(
    const float* __restrict__ x, const int* __restrict__ winners,
    const float* __restrict__ gamma, const float* __restrict__ beta,
    const float* __restrict__ wc, const float* __restrict__ bc)
{
    int n = blockIdx.x, tid = threadIdx.x;
    const float* xr = x + (size_t)n * C_DIM;
    float xv[4], s = 0.f, s2 = 0.f;
#pragma unroll
    for (int i = 0; i < 4; i++) { float v = xr[tid + 256 * i]; xv[i] = v; s += v; s2 += v * v; }
#pragma unroll
    for (int off = 16; off > 0; off >>= 1) {
        s  += __shfl_down_sync(0xffffffffu, s,  off);
        s2 += __shfl_down_sync(0xffffffffu, s2, off);
    }
    __shared__ float sh1[8], sh2[8];
    __shared__ float s_mean, s_rstd;
    int warp = tid >> 5, lane = tid & 31;
    if (lane == 0) { sh1[warp] = s; sh2[warp] = s2; }
    __syncthreads();
    if (tid == 0) {
        float ts = 0.f, ts2 = 0.f;
#pragma unroll
        for (int w = 0; w < 8; w++) { ts += sh1[w]; ts2 += sh2[w]; }
        float mean = ts * (1.f / C_DIM);
        float var = ts2 * (1.f / C_DIM) - mean * mean;
        s_mean = mean; s_rstd = rsqrtf(var + 1e-5f);
    }
    __syncthreads();
    float mean = s_mean, rstd = s_rstd;
    int win = winners[n];
    const float* wcr = wc + (size_t)win * C_DIM;
    float dot = 0.f;
#pragma unroll
    for (int i = 0; i < 4; i++) {
        int c = tid + 256 * i;
        float hv = (xv[i] - mean) * rstd * gamma[c] + beta[c];
        g_h[(size_t)n * C_DIM + c] = hv;
        dot += hv * wcr[c];
    }
#pragma unroll
    for (int off = 16; off > 0; off >>= 1) dot += __shfl_down_sync(0xffffffffu, dot, off);
    if (lane == 0) sh1[warp] = dot;
    __syncthreads();
    if (tid == 0) {
        float t = 0.f;
#pragma unroll
        for (int w = 0; w < 8; w++) t += sh1[w];
        t += bc[win];
        float conf = 1.f / (1.f + expf(-t));
        g_scale[n] = conf / (conf + 1e-6f);
        atomicAdd(&g_count[win], 1);
    }
}

__global__ void scan_kernel() {
    if (threadIdx.x == 0) {
        int acc = 0, pacc = 0;
        g_offset[0] = 0; g_poff[0] = 0;
        for (int e = 0; e < E_NUM; e++) {
            int c = g_count[e];
            acc += c;
            g_offset[e + 1] = acc;
            g_cursor[e] = g_offset[e];
            pacc += ((c + 127) / 128) * 128;
            g_poff[e + 1] = pacc;
        }
    }
}

__global__ void scatter_kernel(const int* __restrict__ winners) {
    int n = blockIdx.x * blockDim.x + threadIdx.x;
    if (n < N_TOK) {
        int e = winners[n];
        int pos = atomicAdd(&g_cursor[e], 1);
        g_sorted[pos] = n;
    }
}

// ---------------------------------------------------------------------------
// HMMA GEMM (R5 core + double-buffered smem).
// CTA 128x128, BK=32, 8 warps (2M x 4N), warp tile 64x32.
// A: gathered fp32 LDG + in-kernel hi/lo bf16 split.
// B: coalesced fp32 column loads + in-kernel hi/lo split (R5-validated pattern).
// Two 40KB smem stages; per chunk: compute(c) -> STS(c+1) -> LDG(c+2) -> sync.
// ---------------------------------------------------------------------------
#define BK 32
#define ROW_STRIDE 80
#define PLANE_B (128 * ROW_STRIDE)   // 10240
#define STAGE_B (4 * PLANE_B)        // 40960

template<bool G1>
__global__ void __launch_bounds__(256, 1) gemm_mma(
    const float* __restrict__ w,      // G1: w1 [E][C][H]; G2: w2 [E][H][C]
    const float* __restrict__ x,
    float* __restrict__ out)
{
    constexpr int K  = G1 ? C_DIM : H_DIM;   // reduction dim
    constexpr int NB = G1 ? H_DIM : C_DIM;   // output-feature dim
    constexpr int NC = K / BK;

    int e     = blockIdx.z;
    int pbase = g_poff[e];
    int pcnt  = g_poff[e + 1] - pbase;
    int row0  = blockIdx.y * 128;
    if (row0 >= pcnt) return;
    int coln0 = blockIdx.x * 128;
    int prow0 = pbase + row0;

    extern __shared__ __align__(16) char sm[];
    uint32_t sb = smem_u32(sm);

    int tid = threadIdx.x, lane = tid & 31, wid = tid >> 5;
    int wm = wid & 1, wn = wid >> 1;
    int g4 = lane >> 2, t4 = lane & 3;

    int obase = g_offset[e];
    int cnt   = g_offset[e + 1] - obase;

    // ---- A source rows: 4 rows per thread, k-quarter kq ----
    int kq = tid & 7;
    const float* asrc[4];
#pragma unroll
    for (int p = 0; p < 4; p++) {
        int m = p * 32 + (tid >> 3);
        if (G1) {
            int gr = row0 + m;
            asrc[p] = (gr < cnt) ? (g_h + (size_t)g_sorted[obase + gr] * C_DIM) : 0;
        } else {
            asrc[p] = g_act + (size_t)(prow0 + m) * H_DIM;
        }
    }
    // ---- B source: one n column per thread, coalesced across lanes ----
    int nb = tid & 127;
    int khalf = tid >> 7;             // 0/1
    const float* bcol = w + (size_t)e * C_DIM * H_DIM + (coln0 + nb);

    float acc[4][4][4];
#pragma unroll
    for (int i = 0; i < 4; i++)
#pragma unroll
        for (int j = 0; j < 4; j++)
#pragma unroll
            for (int q = 0; q < 4; q++) acc[i][j][q] = 0.f;

    // register prefetch buffers
    float4 ra[4];
    float  rb0[8], rb1[8];

    // STS helper (writes chunk in registers into stage base soff)
    auto sts_chunk = [&](uint32_t soff) {
#pragma unroll
        for (int p = 0; p < 4; p++) {
            int m = p * 32 + (tid >> 3);
            uint32_t off = soff + (uint32_t)(m * ROW_STRIDE + 8 * kq);
            uint2 hv, lv;
            hv.x = pack_hi(ra[p].x, ra[p].y); hv.y = pack_hi(ra[p].z, ra[p].w);
            lv.x = pack_lo(ra[p].x, ra[p].y); lv.y = pack_lo(ra[p].z, ra[p].w);
            *reinterpret_cast<uint2*>(sm + off)           = hv;
            *reinterpret_cast<uint2*>(sm + PLANE_B + off) = lv;
        }
#pragma unroll
        for (int p = 0; p < 8; p++) {
            int kp = p * 2 + khalf;
            uint32_t off = soff + (uint32_t)(nb * ROW_STRIDE + 4 * kp);
            *reinterpret_cast<uint32_t*>(sm + 2 * PLANE_B + off) = pack_hi(rb0[p], rb1[p]);
            *reinterpret_cast<uint32_t*>(sm + 3 * PLANE_B + off) = pack_lo(rb0[p], rb1[p]);
        }
    };
    auto ldg_chunk = [&](int c) {
        int k0 = c * BK;
#pragma unroll
        for (int p = 0; p < 4; p++)
            ra[p] = asrc[p] ? *reinterpret_cast<const float4*>(asrc[p] + k0 + 4 * kq)
                            : make_float4(0.f, 0.f, 0.f, 0.f);
#pragma unroll
        for (int p = 0; p < 8; p++) {
            int k = k0 + 2 * (p * 2 + khalf);
            rb0[p] = bcol[(size_t)k * NB];
            rb1[p] = bcol[(size_t)(k + 1) * NB];
        }
    };

    // prologue: chunk0 -> stage0; prefetch chunk1 into regs
    ldg_chunk(0);
    sts_chunk(0);
    if (NC > 1) ldg_chunk(1);
    __syncthreads();

#pragma unroll 1
    for (int c = 0; c < NC; c++) {
        uint32_t st = sb + (uint32_t)(c & 1) * STAGE_B;

        // ---- compute chunk c (validated m16n8k16 fragment layout) ----
#pragma unroll
        for (int ks = 0; ks < 2; ks++) {
            uint32_t ahi[4][4], alo[4][4];
#pragma unroll
            for (int mi = 0; mi < 4; mi++) {
                uint32_t base = st + (uint32_t)((wm * 64 + mi * 16 + g4) * ROW_STRIDE + ks * 32 + t4 * 4);
                ahi[mi][0] = lds32(base);
                ahi[mi][1] = lds32(base + 8 * ROW_STRIDE);
                ahi[mi][2] = lds32(base + 16);
                ahi[mi][3] = lds32(base + 8 * ROW_STRIDE + 16);
                uint32_t basel = base + PLANE_B;
                alo[mi][0] = lds32(basel);
                alo[mi][1] = lds32(basel + 8 * ROW_STRIDE);
                alo[mi][2] = lds32(basel + 16);
                alo[mi][3] = lds32(basel + 8 * ROW_STRIDE + 16);
            }
            uint32_t bhi[4][2], blo[4][2];
#pragma unroll
            for (int nt = 0; nt < 4; nt++) {
                uint32_t bb = st + (uint32_t)(2 * PLANE_B + (wn * 32 + nt * 8 + g4) * ROW_STRIDE + ks * 32 + t4 * 4);
                bhi[nt][0] = lds32(bb);
                bhi[nt][1] = lds32(bb + 16);
                blo[nt][0] = lds32(bb + PLANE_B);
                blo[nt][1] = lds32(bb + PLANE_B + 16);
            }
#pragma unroll
            for (int mi = 0; mi < 4; mi++)
#pragma unroll
                for (int nt = 0; nt < 4; nt++) {
                    float* cc = acc[mi][nt];
                    mma16816(cc, ahi[mi], bhi[nt][0], bhi[nt][1]);
                    mma16816(cc, alo[mi], bhi[nt][0], bhi[nt][1]);
                    mma16816(cc, ahi[mi], blo[nt][0], blo[nt][1]);
                }
        }

        // ---- stage chunk c+1 into the other buffer, prefetch c+2 ----
        if (c + 1 < NC) {
            sts_chunk((uint32_t)((c + 1) & 1) * STAGE_B);
            if (c + 2 < NC) ldg_chunk(c + 2);
            __syncthreads();
        }
    }

    // ---- epilogue (unchanged) ----
    if (G1) {
#pragma unroll
        for (int mi = 0; mi < 4; mi++) {
            int gr = wm * 64 + mi * 16 + g4;
            size_t r0g = (size_t)(prow0 + gr)     * H_DIM;
            size_t r1g = (size_t)(prow0 + gr + 8) * H_DIM;
#pragma unroll
            for (int nt = 0; nt < 4; nt++) {
                int gc = coln0 + wn * 32 + nt * 8 + t4 * 2;
                float* cc = acc[mi][nt];
                float2 v0, v1;
                v0.x = fmaxf(cc[0], 0.f); v0.x *= v0.x;
                v0.y = fmaxf(cc[1], 0.f); v0.y *= v0.y;
                v1.x = fmaxf(cc[2], 0.f); v1.x *= v1.x;
                v1.y = fmaxf(cc[3], 0.f); v1.y *= v1.y;
                *reinterpret_cast<float2*>(g_act + r0g + gc) = v0;
                *reinterpret_cast<float2*>(g_act + r1g + gc) = v1;
            }
        }
    } else {
#pragma unroll
        for (int mi = 0; mi < 4; mi++) {
            int rl0 = row0 + wm * 64 + mi * 16 + g4;
            int tok0 = -1, tok1 = -1;
            float sc0 = 0.f, sc1 = 0.f;
            if (rl0 < cnt)     { tok0 = g_sorted[obase + rl0];     sc0 = g_scale[tok0]; }
            if (rl0 + 8 < cnt) { tok1 = g_sorted[obase + rl0 + 8]; sc1 = g_scale[tok1]; }
#pragma unroll
            for (int nt = 0; nt < 4; nt++) {
                int gc = coln0 + wn * 32 + nt * 8 + t4 * 2;
                float* cc = acc[mi][nt];
                if (tok0 >= 0) {
                    size_t o = (size_t)tok0 * C_DIM + gc;
                    float2 xv = *reinterpret_cast<const float2*>(x + o);
                    float2 ov; ov.x = xv.x + cc[0] * sc0; ov.y = xv.y + cc[1] * sc0;
                    *reinterpret_cast<float2*>(out + o) = ov;
                }
                if (tok1 >= 0) {
                    size_t o = (size_t)tok1 * C_DIM + gc;
                    float2 xv = *reinterpret_cast<const float2*>(x + o);
                    float2 ov; ov.x = xv.x + cc[2] * sc1; ov.y = xv.y + cc[3] * sc1;
                    *reinterpret_cast<float2*>(out + o) = ov;
                }
            }
        }
    }
}

// ---------------------------------------------------------------------------
extern "C" void kernel_launch(void* const* d_in, const int* in_sizes, int n_in,
                              void* d_out, int out_size)
{
    const float* x       = (const float*)d_in[0];
    const int*   winners = (const int*)  d_in[1];
    const float* gamma   = (const float*)d_in[2];
    const float* beta    = (const float*)d_in[3];
    const float* w1      = (const float*)d_in[4];
    const float* w2      = (const float*)d_in[5];
    const float* wc      = (const float*)d_in[6];
    const float* bc      = (const float*)d_in[7];
    float* out = (float*)d_out;

    const int SMEM = 2 * STAGE_B;   // 80 KB dynamic
    cudaFuncSetAttribute(gemm_mma<true>,  cudaFuncAttributeMaxDynamicSharedMemorySize, SMEM);
    cudaFuncSetAttribute(gemm_mma<false>, cudaFuncAttributeMaxDynamicSharedMemorySize, SMEM);

    init_kernel<<<1, 32>>>();
    ln_conf_kernel<<<N_TOK, 256>>>(x, winners, gamma, beta, wc, bc);
    scan_kernel<<<1, 32>>>();
    scatter_kernel<<<N_TOK / 256, 256>>>(winners);

    gemm_mma<true><<<dim3(H_DIM / 128, PADDED_CAP / 128, E_NUM), 256, SMEM>>>(w1, x, out);
    gemm_mma<false><<<dim3(C_DIM / 128, PADDED_CAP / 128, E_NUM), 256, SMEM>>>(w2, x, out);
}